// round 2
// baseline (speedup 1.0000x reference)
#include <cuda_runtime.h>
#include <math.h>

#define NB   16
#define CINC 256
#define DIMC 32
#define HH   128
#define WW   128
#define PIX  (HH*WW)          // 16384
#define NA   192
#define NR   192
#define APIX (NA*NR)          // 36864
#define BN_EPS 1e-5f

// ---------------- device scratch (static allocations only) ----------------
__device__ double        g_tabs[NA];
__device__ double        g_tabc[NA];
__device__ unsigned char g_ridx[(size_t)PIX * NA];              // [p][a]
__device__ float         g_h1[(size_t)NB * PIX * DIMC];         // [n][p][c]  conv1 pre-BN
__device__ float         g_acc[(size_t)NB * DIMC * NA * NR];    // [n][c][a][r]
__device__ float         g_h2[(size_t)NB * DIMC * NA * NR];     // conv2 pre-BN
__device__ float         g_part1[512  * DIMC * 2];
__device__ float         g_part2[2304 * DIMC * 2];
__device__ float         g_part3[2304 * DIMC * 2];
__device__ float         g_scale1[DIMC], g_shift1[DIMC];
__device__ float         g_scale2[DIMC], g_shift2[DIMC];
__device__ float         g_scale3[DIMC], g_shift3[DIMC];

// ---------------- angle tables (double, matches numpy float64) ------------
__global__ void k_tab() {
    int a = threadIdx.x;
    if (a < NA) {
        double irho = 182.0 / 191.0;                 // float(int(sqrt(128^2+128^2)+1))/(192-1)
        double th = (double)a * (3.141592653589793 / 192.0);
        g_tabs[a] = sin(th) / irho;
        g_tabc[a] = cos(th) / irho;
    }
}

// ---------------- rho index LUT:  g_ridx[p][a] ------------------------------
__global__ void k_lut() {
    int i = blockIdx.x * 256 + threadIdx.x;          // i over PIX*NA
    if (i >= PIX * NA) return;
    int p = i / NA, a = i % NA;
    int x = p % WW, y = p / WW;
    // forbid FMA fusion: mul+mul+add exactly like numpy
    double v = __dadd_rn(__dmul_rn((double)(x - WW / 2), g_tabc[a]),
                         __dmul_rn((double)(y - HH / 2), g_tabs[a]));
    int r = (int)rint(v) + NR / 2;                   // rint = round-half-even, like np.round
    r = min(max(r, 0), NR - 1);
    g_ridx[i] = (unsigned char)r;
}

// ---------------- conv1 (1x1) + fused BN1 partial stats --------------------
// block: 256 threads = 64 pixel-groups x 4 d-groups; thread: 8p x 8d
__global__ __launch_bounds__(256) void k_conv1(const float* __restrict__ x,
                                               const float* __restrict__ w1,
                                               const float* __restrict__ b1) {
    __shared__ float sW[CINC * DIMC];   // [ci][d]  32KB
    __shared__ float sX[4][512];        // 8KB chunk
    __shared__ float sS[DIMC], sQ[DIMC];

    int tid = threadIdx.x;
    int n  = blockIdx.x >> 5;
    int p0 = (blockIdx.x & 31) * 512;

    for (int i = tid; i < CINC * DIMC; i += 256) {
        int ci = i >> 5, d = i & 31;
        sW[i] = w1[d * CINC + ci];
    }
    if (tid < DIMC) { sS[tid] = 0.f; sQ[tid] = 0.f; }

    int pl = tid & 63;
    int d0 = (tid >> 6) * 8;

    float acc[8][8];
#pragma unroll
    for (int j = 0; j < 8; j++)
#pragma unroll
        for (int k = 0; k < 8; k++) acc[j][k] = 0.f;

    const float* xb = x + (size_t)n * CINC * PIX + p0;

    for (int cc = 0; cc < CINC; cc += 4) {
        __syncthreads();
        for (int i = tid; i < 4 * 512; i += 256) {
            int cl = i >> 9, pp = i & 511;
            sX[cl][pp] = xb[(size_t)(cc + cl) * PIX + pp];
        }
        __syncthreads();
#pragma unroll
        for (int cl = 0; cl < 4; cl++) {
            float xv[8];
#pragma unroll
            for (int j = 0; j < 8; j++) xv[j] = sX[cl][pl + 64 * j];
            const float* wp = &sW[(cc + cl) * DIMC + d0];
            float4 wa = *(const float4*)wp;
            float4 wb = *(const float4*)(wp + 4);
            float wr[8] = {wa.x, wa.y, wa.z, wa.w, wb.x, wb.y, wb.z, wb.w};
#pragma unroll
            for (int j = 0; j < 8; j++)
#pragma unroll
                for (int k = 0; k < 8; k++) acc[j][k] = fmaf(xv[j], wr[k], acc[j][k]);
        }
    }

    float bia[8];
#pragma unroll
    for (int k = 0; k < 8; k++) bia[k] = b1[d0 + k];

    float* hb = g_h1 + ((size_t)n * PIX + p0) * DIMC;
    float sl[8], ql[8];
#pragma unroll
    for (int k = 0; k < 8; k++) { sl[k] = 0.f; ql[k] = 0.f; }

#pragma unroll
    for (int j = 0; j < 8; j++) {
#pragma unroll
        for (int k = 0; k < 8; k++) {
            float v = acc[j][k] + bia[k];
            acc[j][k] = v;
            sl[k] += v; ql[k] += v * v;
        }
        float* op = hb + (size_t)(pl + 64 * j) * DIMC + d0;
        *(float4*)op       = make_float4(acc[j][0], acc[j][1], acc[j][2], acc[j][3]);
        *(float4*)(op + 4) = make_float4(acc[j][4], acc[j][5], acc[j][6], acc[j][7]);
    }
#pragma unroll
    for (int k = 0; k < 8; k++) {
        atomicAdd(&sS[d0 + k], sl[k]);
        atomicAdd(&sQ[d0 + k], ql[k]);
    }
    __syncthreads();
    if (tid < DIMC) {
        g_part1[(blockIdx.x * DIMC + tid) * 2 + 0] = sS[tid];
        g_part1[(blockIdx.x * DIMC + tid) * 2 + 1] = sQ[tid];
    }
}

// ---------------- BN reduce: partials -> scale/shift ------------------------
__global__ void k_red(int which, int nb, float cnt,
                      const float* __restrict__ g, const float* __restrict__ be) {
    const float* part = (which == 1) ? g_part1 : (which == 2) ? g_part2 : g_part3;
    float* sc = (which == 1) ? g_scale1 : (which == 2) ? g_scale2 : g_scale3;
    float* sh = (which == 1) ? g_shift1 : (which == 2) ? g_shift2 : g_shift3;
    __shared__ float rs[8][32], rq[8][32];
    int ch = threadIdx.x & 31, s = threadIdx.x >> 5;
    float su = 0.f, q = 0.f;
    for (int b = s; b < nb; b += 8) {
        su += part[((size_t)b * DIMC + ch) * 2 + 0];
        q  += part[((size_t)b * DIMC + ch) * 2 + 1];
    }
    rs[s][ch] = su; rq[s][ch] = q;
    __syncthreads();
    if (threadIdx.x < 32) {
        float S = 0.f, Q = 0.f;
        for (int t = 0; t < 8; t++) { S += rs[t][ch]; Q += rq[t][ch]; }
        float m   = S / cnt;
        float var = Q / cnt - m * m;
        float scv = g[ch] * rsqrtf(var + BN_EPS);
        sc[ch] = scv;
        sh[ch] = be[ch] - m * scv;
    }
}

// ---------------- DHT: smem-atomic scatter, 4 angles / block ----------------
// block (a-group, n): 8 warps; warp = 32 channels of one pixel
__global__ __launch_bounds__(256) void k_dht() {
    extern __shared__ float sAcc[];             // [4][NR*33]
    const int RS = NR * 33;
    int tid = threadIdx.x;
    int n  = blockIdx.y;
    int a0 = blockIdx.x * 4;

    for (int i = tid; i < 4 * RS; i += 256) sAcc[i] = 0.f;
    __syncthreads();

    int c = tid & 31, w = tid >> 5;
    float sc = g_scale1[c], sh = g_shift1[c];
    const float* hb = g_h1 + (size_t)n * PIX * DIMC;

    for (int p = w; p < PIX; p += 8) {
        float v = hb[(size_t)p * DIMC + c];
        v = fmaxf(fmaf(v, sc, sh), 0.f);
        unsigned int packed = *(const unsigned int*)(g_ridx + (size_t)p * NA + a0);
        if (v > 0.f) {
#pragma unroll
            for (int gg = 0; gg < 4; gg++) {
                int r = (packed >> (8 * gg)) & 255;
                atomicAdd(&sAcc[gg * RS + r * 33 + c], v);
            }
        }
    }
    __syncthreads();

    for (int e = tid; e < 4 * NR * DIMC; e += 256) {
        int r  = e % NR;
        int c2 = (e / NR) & 31;
        int gg = e / (NR * DIMC);
        g_acc[(((size_t)n * DIMC + c2) * NA + (a0 + gg)) * NR + r] = sAcc[gg * RS + r * 33 + c2];
    }
}

// ---------------- 3x3 conv + fused BN partial stats -------------------------
// MODE 0: in = g_acc (raw)            -> out g_h2,  part2
// MODE 1: in = g_h2 (apply BN2+ReLU)  -> out d_out, part3
template <int MODE>
__global__ __launch_bounds__(256) void k_conv3x3(const float* __restrict__ w,
                                                 const float* __restrict__ b,
                                                 float* __restrict__ out_ext) {
    extern __shared__ float sm[];
    float* sIn = sm;                 // 32*18*18
    float* sW  = sm + 32 * 324;      // 32*9*32
    __shared__ float sS[DIMC], sQ[DIMC];

    int tid = threadIdx.x;
    if (tid < DIMC) { sS[tid] = 0.f; sQ[tid] = 0.f; }

    int n   = blockIdx.z;
    int ty0 = blockIdx.y * 16, tx0 = blockIdx.x * 16;

    for (int i = tid; i < 32 * 9 * 32; i += 256) {
        int d = i & 31; int t = (i >> 5) % 9; int cc = i / 288;
        sW[i] = w[((size_t)d * 32 + cc) * 9 + t];
    }

    const float* in = (MODE == 0) ? g_acc : g_h2;
    for (int i = tid; i < 32 * 324; i += 256) {
        int cc = i / 324; int rem = i % 324;
        int yy = rem / 18, xx = rem % 18;
        int gy = ty0 + yy - 1, gx = tx0 + xx - 1;
        float v = 0.f;
        if ((unsigned)gy < 192u && (unsigned)gx < 192u) {
            v = in[(((size_t)n * DIMC + cc) * 192 + gy) * 192 + gx];
            if (MODE == 1) v = fmaxf(fmaf(v, g_scale2[cc], g_shift2[cc]), 0.f);
        }
        sIn[i] = v;
    }
    __syncthreads();

    int pg = tid & 63, d0 = (tid >> 6) * 8;
    int px = pg & 15, pyb = pg >> 4;

    float acc[4][8];
#pragma unroll
    for (int j = 0; j < 4; j++)
#pragma unroll
        for (int k = 0; k < 8; k++) acc[j][k] = 0.f;

    for (int cc = 0; cc < 32; cc++) {
        const float* ib = &sIn[cc * 324];
        const float* wb = &sW[cc * 288 + d0];
#pragma unroll
        for (int t = 0; t < 9; t++) {
            int ky = t / 3, kx = t % 3;
            float4 wa = *(const float4*)(wb + t * 32);
            float4 wc = *(const float4*)(wb + t * 32 + 4);
            float wr[8] = {wa.x, wa.y, wa.z, wa.w, wc.x, wc.y, wc.z, wc.w};
#pragma unroll
            for (int j = 0; j < 4; j++) {
                float xv = ib[(pyb + 4 * j + ky) * 18 + px + kx];
#pragma unroll
                for (int k = 0; k < 8; k++) acc[j][k] = fmaf(xv, wr[k], acc[j][k]);
            }
        }
    }

    float bia[8];
#pragma unroll
    for (int k = 0; k < 8; k++) bia[k] = b[d0 + k];

    float* outp = (MODE == 0) ? g_h2 : out_ext;
    float sl[8], ql[8];
#pragma unroll
    for (int k = 0; k < 8; k++) { sl[k] = 0.f; ql[k] = 0.f; }

#pragma unroll
    for (int j = 0; j < 4; j++) {
        int oy = ty0 + pyb + 4 * j, ox = tx0 + px;
#pragma unroll
        for (int k = 0; k < 8; k++) {
            float v = acc[j][k] + bia[k];
            outp[(((size_t)n * DIMC + d0 + k) * 192 + oy) * 192 + ox] = v;
            sl[k] += v; ql[k] += v * v;
        }
    }
#pragma unroll
    for (int k = 0; k < 8; k++) {
        atomicAdd(&sS[d0 + k], sl[k]);
        atomicAdd(&sQ[d0 + k], ql[k]);
    }
    __syncthreads();
    int bid = (blockIdx.z * gridDim.y + blockIdx.y) * gridDim.x + blockIdx.x;
    float* part = (MODE == 0) ? g_part2 : g_part3;
    if (tid < DIMC) {
        part[((size_t)bid * DIMC + tid) * 2 + 0] = sS[tid];
        part[((size_t)bid * DIMC + tid) * 2 + 1] = sQ[tid];
    }
}

// ---------------- final in-place BN3 + ReLU on d_out ------------------------
__global__ void k_final(float* __restrict__ out) {
    size_t i = ((size_t)blockIdx.x * 256 + threadIdx.x) * 4;
    int c = (int)((i / APIX) & 31);
    float sc = g_scale3[c], sh = g_shift3[c];
    float4 v = *(float4*)(out + i);
    v.x = fmaxf(fmaf(v.x, sc, sh), 0.f);
    v.y = fmaxf(fmaf(v.y, sc, sh), 0.f);
    v.z = fmaxf(fmaf(v.z, sc, sh), 0.f);
    v.w = fmaxf(fmaf(v.w, sc, sh), 0.f);
    *(float4*)(out + i) = v;
}

// ---------------- launch ----------------------------------------------------
extern "C" void kernel_launch(void* const* d_in, const int* in_sizes, int n_in,
                              void* d_out, int out_size) {
    const float* x   = (const float*)d_in[0];
    const float* w1  = (const float*)d_in[1];
    const float* b1  = (const float*)d_in[2];
    const float* g1  = (const float*)d_in[3];
    const float* be1 = (const float*)d_in[4];
    const float* w2  = (const float*)d_in[5];
    const float* b2  = (const float*)d_in[6];
    const float* g2  = (const float*)d_in[7];
    const float* be2 = (const float*)d_in[8];
    const float* w3  = (const float*)d_in[9];
    const float* b3  = (const float*)d_in[10];
    const float* g3  = (const float*)d_in[11];
    const float* be3 = (const float*)d_in[12];
    float* out = (float*)d_out;

    const int dhtSmem  = 4 * NR * 33 * 4;                  // 101376
    const int convSmem = (32 * 324 + 32 * 9 * 32) * 4;     // 78336
    cudaFuncSetAttribute(k_dht,        cudaFuncAttributeMaxDynamicSharedMemorySize, dhtSmem);
    cudaFuncSetAttribute(k_conv3x3<0>, cudaFuncAttributeMaxDynamicSharedMemorySize, convSmem);
    cudaFuncSetAttribute(k_conv3x3<1>, cudaFuncAttributeMaxDynamicSharedMemorySize, convSmem);

    k_tab<<<1, 192>>>();
    k_lut<<<(PIX * NA) / 256, 256>>>();

    k_conv1<<<512, 256>>>(x, w1, b1);
    k_red<<<1, 256>>>(1, 512, (float)(NB * PIX), g1, be1);

    k_dht<<<dim3(48, NB), 256, dhtSmem>>>();

    dim3 cgrid(12, 12, NB);
    k_conv3x3<0><<<cgrid, 256, convSmem>>>(w2, b2, nullptr);
    k_red<<<1, 256>>>(2, 2304, (float)(NB * APIX), g2, be2);

    k_conv3x3<1><<<cgrid, 256, convSmem>>>(w3, b3, out);
    k_red<<<1, 256>>>(3, 2304, (float)(NB * APIX), g3, be3);

    k_final<<<(NB * DIMC * APIX) / (256 * 4), 256>>>(out);
}

// round 3
// speedup vs baseline: 1.8647x; 1.8647x over previous
#include <cuda_runtime.h>
#include <math.h>

#define NB   16
#define CINC 256
#define DIMC 32
#define HH   128
#define WW   128
#define PIX  (HH*WW)          // 16384
#define NA   192
#define NR   192
#define APIX (NA*NR)          // 36864
#define BN_EPS 1e-5f
#define RUNCAP 132

// ---------------- device scratch (static allocations only) ----------------
__device__ double        g_tabs[NA];
__device__ double        g_tabc[NA];
__device__ unsigned int  g_runs[(size_t)NA * HH * RUNCAP];      // [a][y][slot] = xs | r<<8
__device__ int           g_nrun[NA * HH];
__device__ float         g_h1[(size_t)NB * PIX * DIMC];         // [n][p][c]  conv1 pre-BN
__device__ float         g_pref[(size_t)NB * HH * 129 * DIMC];  // [n][y][x+1][c] prefix of relu(bn(h1))
__device__ float         g_acc[(size_t)NB * DIMC * NA * NR];    // [n][c][a][r]
__device__ float         g_h2[(size_t)NB * DIMC * NA * NR];     // conv2 pre-BN
__device__ float         g_part1[512  * DIMC * 2];
__device__ float         g_part2[2304 * DIMC * 2];
__device__ float         g_part3[2304 * DIMC * 2];
__device__ float         g_scale1[DIMC], g_shift1[DIMC];
__device__ float         g_scale2[DIMC], g_shift2[DIMC];
__device__ float         g_scale3[DIMC], g_shift3[DIMC];

// ---------------- angle tables (double, matches numpy float64) ------------
__global__ void k_tab() {
    int a = threadIdx.x;
    if (a < NA) {
        double irho = 182.0 / 191.0;                 // float(int(sqrt(128^2+128^2)+1))/(192-1)
        double th = (double)a * (3.141592653589793 / 192.0);
        g_tabs[a] = sin(th) / irho;
        g_tabc[a] = cos(th) / irho;
    }
}

// ---------------- run-list builder: per (a,y) contiguous rho runs -----------
__global__ void k_runs() {
    __shared__ int sr[128];
    __shared__ int swcnt[4];
    __shared__ int swoff[4];
    int a = blockIdx.x, y = blockIdx.y;
    int x = threadIdx.x;
    // identical rounding to numpy: mul+mul+add in double, rint (half-even)
    double v = __dadd_rn(__dmul_rn((double)(x - WW / 2), g_tabc[a]),
                         __dmul_rn((double)(y - HH / 2), g_tabs[a]));
    int r = (int)rint(v) + NR / 2;
    r = min(max(r, 0), NR - 1);
    sr[x] = r;
    __syncthreads();
    int f = (x == 0) || (r != sr[x - 1]);
    unsigned bal = __ballot_sync(0xffffffffu, f);
    int w = x >> 5, lane = x & 31;
    int pre = __popc(bal & ((1u << lane) - 1u));
    if (lane == 31) swcnt[w] = __popc(bal);
    __syncthreads();
    if (x == 0) {
        int o = 0;
        for (int i = 0; i < 4; i++) { swoff[i] = o; o += swcnt[i]; }
        g_nrun[a * HH + y] = o;
        g_runs[((size_t)a * HH + y) * RUNCAP + o] = 128u;   // sentinel (xe of last run)
    }
    __syncthreads();
    if (f) g_runs[((size_t)a * HH + y) * RUNCAP + swoff[w] + pre] =
               (unsigned)x | ((unsigned)r << 8);
}

// ---------------- conv1 (1x1) + fused BN1 partial stats --------------------
__global__ __launch_bounds__(256) void k_conv1(const float* __restrict__ x,
                                               const float* __restrict__ w1,
                                               const float* __restrict__ b1) {
    __shared__ float sW[CINC * DIMC];
    __shared__ float sX[4][512];
    __shared__ float sS[DIMC], sQ[DIMC];

    int tid = threadIdx.x;
    int n  = blockIdx.x >> 5;
    int p0 = (blockIdx.x & 31) * 512;

    for (int i = tid; i < CINC * DIMC; i += 256) {
        int ci = i >> 5, d = i & 31;
        sW[i] = w1[d * CINC + ci];
    }
    if (tid < DIMC) { sS[tid] = 0.f; sQ[tid] = 0.f; }

    int pl = tid & 63;
    int d0 = (tid >> 6) * 8;

    float acc[8][8];
#pragma unroll
    for (int j = 0; j < 8; j++)
#pragma unroll
        for (int k = 0; k < 8; k++) acc[j][k] = 0.f;

    const float* xb = x + (size_t)n * CINC * PIX + p0;

    for (int cc = 0; cc < CINC; cc += 4) {
        __syncthreads();
        for (int i = tid; i < 4 * 512; i += 256) {
            int cl = i >> 9, pp = i & 511;
            sX[cl][pp] = xb[(size_t)(cc + cl) * PIX + pp];
        }
        __syncthreads();
#pragma unroll
        for (int cl = 0; cl < 4; cl++) {
            float xv[8];
#pragma unroll
            for (int j = 0; j < 8; j++) xv[j] = sX[cl][pl + 64 * j];
            const float* wp = &sW[(cc + cl) * DIMC + d0];
            float4 wa = *(const float4*)wp;
            float4 wb = *(const float4*)(wp + 4);
            float wr[8] = {wa.x, wa.y, wa.z, wa.w, wb.x, wb.y, wb.z, wb.w};
#pragma unroll
            for (int j = 0; j < 8; j++)
#pragma unroll
                for (int k = 0; k < 8; k++) acc[j][k] = fmaf(xv[j], wr[k], acc[j][k]);
        }
    }

    float bia[8];
#pragma unroll
    for (int k = 0; k < 8; k++) bia[k] = b1[d0 + k];

    float* hb = g_h1 + ((size_t)n * PIX + p0) * DIMC;
    float sl[8], ql[8];
#pragma unroll
    for (int k = 0; k < 8; k++) { sl[k] = 0.f; ql[k] = 0.f; }

#pragma unroll
    for (int j = 0; j < 8; j++) {
#pragma unroll
        for (int k = 0; k < 8; k++) {
            float v = acc[j][k] + bia[k];
            acc[j][k] = v;
            sl[k] += v; ql[k] += v * v;
        }
        float* op = hb + (size_t)(pl + 64 * j) * DIMC + d0;
        *(float4*)op       = make_float4(acc[j][0], acc[j][1], acc[j][2], acc[j][3]);
        *(float4*)(op + 4) = make_float4(acc[j][4], acc[j][5], acc[j][6], acc[j][7]);
    }
#pragma unroll
    for (int k = 0; k < 8; k++) {
        atomicAdd(&sS[d0 + k], sl[k]);
        atomicAdd(&sQ[d0 + k], ql[k]);
    }
    __syncthreads();
    if (tid < DIMC) {
        g_part1[(blockIdx.x * DIMC + tid) * 2 + 0] = sS[tid];
        g_part1[(blockIdx.x * DIMC + tid) * 2 + 1] = sQ[tid];
    }
}

// ---------------- BN reduce: partials -> scale/shift ------------------------
__global__ void k_red(int which, int nb, float cnt,
                      const float* __restrict__ g, const float* __restrict__ be) {
    const float* part = (which == 1) ? g_part1 : (which == 2) ? g_part2 : g_part3;
    float* sc = (which == 1) ? g_scale1 : (which == 2) ? g_scale2 : g_scale3;
    float* sh = (which == 1) ? g_shift1 : (which == 2) ? g_shift2 : g_shift3;
    __shared__ float rs[8][32], rq[8][32];
    int ch = threadIdx.x & 31, s = threadIdx.x >> 5;
    float su = 0.f, q = 0.f;
    for (int b = s; b < nb; b += 8) {
        su += part[((size_t)b * DIMC + ch) * 2 + 0];
        q  += part[((size_t)b * DIMC + ch) * 2 + 1];
    }
    rs[s][ch] = su; rq[s][ch] = q;
    __syncthreads();
    if (threadIdx.x < 32) {
        float S = 0.f, Q = 0.f;
        for (int t = 0; t < 8; t++) { S += rs[t][ch]; Q += rq[t][ch]; }
        float m   = S / cnt;
        float var = Q / cnt - m * m;
        float scv = g[ch] * rsqrtf(var + BN_EPS);
        sc[ch] = scv;
        sh[ch] = be[ch] - m * scv;
    }
}

// ---------------- row prefix sums of relu(bn(h1)) ---------------------------
// warp = one (n,y) row; lane = channel. P[0]=0, P[x+1]=P[x]+v
__global__ __launch_bounds__(256) void k_prefix() {
    int tid = threadIdx.x;
    int w = tid >> 5, c = tid & 31;
    int row = blockIdx.x * 8 + w;                 // n*128 + y
    int n = row >> 7, y = row & 127;
    float sc = g_scale1[c], sh = g_shift1[c];
    const float* hb = g_h1 + ((size_t)n * PIX + (size_t)y * WW) * DIMC + c;
    float* pb = g_pref + (size_t)row * 129 * DIMC + c;
    float s = 0.f;
    pb[0] = 0.f;
#pragma unroll 4
    for (int x = 0; x < 128; x++) {
        float v = fmaxf(fmaf(hb[(size_t)x * DIMC], sc, sh), 0.f);
        s += v;
        pb[(size_t)(x + 1) * DIMC] = s;
    }
}

// ---------------- DHT gather: runs + prefix diffs, no atomics ----------------
// block = (n, 4 angles), 512 threads = 16 warps, 4 warps per angle.
// lane = (run_sub 0..3, channel-quad 0..7). Distinct rho per run => race-free RMW.
__global__ __launch_bounds__(512) void k_dhtg() {
    extern __shared__ float sm[];
    float* sAcc = sm;                               // [4][192][36]
    float* sRow = sm + 4 * 192 * 36;                // [129][32]
    unsigned* sRuns = (unsigned*)(sRow + 129 * 32); // [4][RUNCAP]
    __shared__ int sNr[4];

    int tid = threadIdx.x;
    int n = blockIdx.y, a0 = blockIdx.x * 4;

    for (int i = tid; i < 4 * 192 * 36; i += 512) sAcc[i] = 0.f;

    int w = tid >> 5, lane = tid & 31;
    int ga = w >> 2, ws = w & 3;
    int rsub = lane >> 3, c4 = lane & 7;

    const float4* prefn = (const float4*)(g_pref + (size_t)n * HH * 129 * DIMC);
    float* accA = sAcc + ga * 192 * 36;

    for (int y = 0; y < 128; y++) {
        __syncthreads();
        const float4* src = prefn + (size_t)y * (129 * 8);
        float4* dst = (float4*)sRow;
        for (int i = tid; i < 129 * 8; i += 512) dst[i] = src[i];
        for (int i = tid; i < 4 * RUNCAP; i += 512) {
            int aa = i / RUNCAP, k = i % RUNCAP;
            sRuns[i] = g_runs[((size_t)(a0 + aa) * HH + y) * RUNCAP + k];
        }
        if (tid < 4) sNr[tid] = g_nrun[(a0 + tid) * HH + y];
        __syncthreads();

        int nrun = sNr[ga];
        const unsigned* rl = sRuns + ga * RUNCAP;
        for (int base = ws * 4 + rsub; base < nrun; base += 16) {
            unsigned rec = rl[base], nxt = rl[base + 1];
            int xs = rec & 255, xe = nxt & 255, r = (rec >> 8) & 255;
            float4 pe = ((const float4*)sRow)[xe * 8 + c4];
            float4 ps = ((const float4*)sRow)[xs * 8 + c4];
            float4* ap = (float4*)(accA + r * 36) + c4;
            float4 av = *ap;
            av.x += pe.x - ps.x; av.y += pe.y - ps.y;
            av.z += pe.z - ps.z; av.w += pe.w - ps.w;
            *ap = av;
        }
    }
    __syncthreads();

    for (int e = tid; e < 4 * DIMC * NR; e += 512) {
        int r = e % NR;
        int t = e / NR;
        int c = t & 31;
        int ga2 = t >> 5;
        g_acc[(((size_t)n * DIMC + c) * NA + (a0 + ga2)) * NR + r] =
            sAcc[(ga2 * 192 + r) * 36 + c];
    }
}

// ---------------- 3x3 conv + fused BN partial stats -------------------------
template <int MODE>
__global__ __launch_bounds__(256) void k_conv3x3(const float* __restrict__ w,
                                                 const float* __restrict__ b,
                                                 float* __restrict__ out_ext) {
    extern __shared__ float sm[];
    float* sIn = sm;                 // 32*18*18
    float* sW  = sm + 32 * 324;      // 32*9*32
    __shared__ float sS[DIMC], sQ[DIMC];

    int tid = threadIdx.x;
    if (tid < DIMC) { sS[tid] = 0.f; sQ[tid] = 0.f; }

    int n   = blockIdx.z;
    int ty0 = blockIdx.y * 16, tx0 = blockIdx.x * 16;

    for (int i = tid; i < 32 * 9 * 32; i += 256) {
        int d = i & 31; int t = (i >> 5) % 9; int cc = i / 288;
        sW[i] = w[((size_t)d * 32 + cc) * 9 + t];
    }

    const float* in = (MODE == 0) ? g_acc : g_h2;
    for (int i = tid; i < 32 * 324; i += 256) {
        int cc = i / 324; int rem = i % 324;
        int yy = rem / 18, xx = rem % 18;
        int gy = ty0 + yy - 1, gx = tx0 + xx - 1;
        float v = 0.f;
        if ((unsigned)gy < 192u && (unsigned)gx < 192u) {
            v = in[(((size_t)n * DIMC + cc) * 192 + gy) * 192 + gx];
            if (MODE == 1) v = fmaxf(fmaf(v, g_scale2[cc], g_shift2[cc]), 0.f);
        }
        sIn[i] = v;
    }
    __syncthreads();

    int pg = tid & 63, d0 = (tid >> 6) * 8;
    int px = pg & 15, pyb = pg >> 4;

    float acc[4][8];
#pragma unroll
    for (int j = 0; j < 4; j++)
#pragma unroll
        for (int k = 0; k < 8; k++) acc[j][k] = 0.f;

    for (int cc = 0; cc < 32; cc++) {
        const float* ib = &sIn[cc * 324];
        const float* wb = &sW[cc * 288 + d0];
#pragma unroll
        for (int t = 0; t < 9; t++) {
            int ky = t / 3, kx = t % 3;
            float4 wa = *(const float4*)(wb + t * 32);
            float4 wc = *(const float4*)(wb + t * 32 + 4);
            float wr[8] = {wa.x, wa.y, wa.z, wa.w, wc.x, wc.y, wc.z, wc.w};
#pragma unroll
            for (int j = 0; j < 4; j++) {
                float xv = ib[(pyb + 4 * j + ky) * 18 + px + kx];
#pragma unroll
                for (int k = 0; k < 8; k++) acc[j][k] = fmaf(xv, wr[k], acc[j][k]);
            }
        }
    }

    float bia[8];
#pragma unroll
    for (int k = 0; k < 8; k++) bia[k] = b[d0 + k];

    float* outp = (MODE == 0) ? g_h2 : out_ext;
    float sl[8], ql[8];
#pragma unroll
    for (int k = 0; k < 8; k++) { sl[k] = 0.f; ql[k] = 0.f; }

#pragma unroll
    for (int j = 0; j < 4; j++) {
        int oy = ty0 + pyb + 4 * j, ox = tx0 + px;
#pragma unroll
        for (int k = 0; k < 8; k++) {
            float v = acc[j][k] + bia[k];
            outp[(((size_t)n * DIMC + d0 + k) * 192 + oy) * 192 + ox] = v;
            sl[k] += v; ql[k] += v * v;
        }
    }
#pragma unroll
    for (int k = 0; k < 8; k++) {
        atomicAdd(&sS[d0 + k], sl[k]);
        atomicAdd(&sQ[d0 + k], ql[k]);
    }
    __syncthreads();
    int bid = (blockIdx.z * gridDim.y + blockIdx.y) * gridDim.x + blockIdx.x;
    float* part = (MODE == 0) ? g_part2 : g_part3;
    if (tid < DIMC) {
        part[((size_t)bid * DIMC + tid) * 2 + 0] = sS[tid];
        part[((size_t)bid * DIMC + tid) * 2 + 1] = sQ[tid];
    }
}

// ---------------- final in-place BN3 + ReLU on d_out ------------------------
__global__ void k_final(float* __restrict__ out) {
    size_t i = ((size_t)blockIdx.x * 256 + threadIdx.x) * 4;
    int c = (int)((i / APIX) & 31);
    float sc = g_scale3[c], sh = g_shift3[c];
    float4 v = *(float4*)(out + i);
    v.x = fmaxf(fmaf(v.x, sc, sh), 0.f);
    v.y = fmaxf(fmaf(v.y, sc, sh), 0.f);
    v.z = fmaxf(fmaf(v.z, sc, sh), 0.f);
    v.w = fmaxf(fmaf(v.w, sc, sh), 0.f);
    *(float4*)(out + i) = v;
}

// ---------------- launch ----------------------------------------------------
extern "C" void kernel_launch(void* const* d_in, const int* in_sizes, int n_in,
                              void* d_out, int out_size) {
    const float* x   = (const float*)d_in[0];
    const float* w1  = (const float*)d_in[1];
    const float* b1  = (const float*)d_in[2];
    const float* g1  = (const float*)d_in[3];
    const float* be1 = (const float*)d_in[4];
    const float* w2  = (const float*)d_in[5];
    const float* b2  = (const float*)d_in[6];
    const float* g2  = (const float*)d_in[7];
    const float* be2 = (const float*)d_in[8];
    const float* w3  = (const float*)d_in[9];
    const float* b3  = (const float*)d_in[10];
    const float* g3  = (const float*)d_in[11];
    const float* be3 = (const float*)d_in[12];
    float* out = (float*)d_out;

    const int dhtSmem  = (4 * 192 * 36 + 129 * 32) * 4 + 4 * RUNCAP * 4;  // 129216
    const int convSmem = (32 * 324 + 32 * 9 * 32) * 4;                    // 78336
    cudaFuncSetAttribute(k_dhtg,       cudaFuncAttributeMaxDynamicSharedMemorySize, dhtSmem);
    cudaFuncSetAttribute(k_conv3x3<0>, cudaFuncAttributeMaxDynamicSharedMemorySize, convSmem);
    cudaFuncSetAttribute(k_conv3x3<1>, cudaFuncAttributeMaxDynamicSharedMemorySize, convSmem);

    k_tab<<<1, 192>>>();
    k_runs<<<dim3(NA, HH), 128>>>();

    k_conv1<<<512, 256>>>(x, w1, b1);
    k_red<<<1, 256>>>(1, 512, (float)(NB * PIX), g1, be1);

    k_prefix<<<256, 256>>>();
    k_dhtg<<<dim3(48, NB), 512, dhtSmem>>>();

    dim3 cgrid(12, 12, NB);
    k_conv3x3<0><<<cgrid, 256, convSmem>>>(w2, b2, nullptr);
    k_red<<<1, 256>>>(2, 2304, (float)(NB * APIX), g2, be2);

    k_conv3x3<1><<<cgrid, 256, convSmem>>>(w3, b3, out);
    k_red<<<1, 256>>>(3, 2304, (float)(NB * APIX), g3, be3);

    k_final<<<(NB * DIMC * APIX) / (256 * 4), 256>>>(out);
}

// round 4
// speedup vs baseline: 2.2627x; 1.2135x over previous
#include <cuda_runtime.h>
#include <math.h>

#define NB   16
#define CINC 256
#define DIMC 32
#define HH   128
#define WW   128
#define PIX  (HH*WW)          // 16384
#define NA   192
#define NR   192
#define APIX (NA*NR)          // 36864
#define BN_EPS 1e-5f
#define RUNCAP 132

typedef unsigned long long ull;

// packed fp32x2 helpers (FFMA2 — ptxas never auto-fuses, must use PTX)
__device__ __forceinline__ void fma2(ull& d, ull a, ull b) {
    asm("fma.rn.f32x2 %0, %1, %2, %0;" : "+l"(d) : "l"(a), "l"(b));
}
__device__ __forceinline__ ull pack2(float x) {
    ull r; asm("mov.b64 %0, {%1, %1};" : "=l"(r) : "f"(x)); return r;
}
__device__ __forceinline__ void unpack2(ull v, float& lo, float& hi) {
    asm("mov.b64 {%0, %1}, %2;" : "=f"(lo), "=f"(hi) : "l"(v));
}

// ---------------- device scratch (static allocations only) ----------------
__device__ double        g_tabs[NA];
__device__ double        g_tabc[NA];
__device__ unsigned int  g_runs[(size_t)NA * HH * RUNCAP];      // [a][y][slot] = xs | r<<8
__device__ int           g_nrun[NA * HH];
__device__ float         g_h1[(size_t)NB * PIX * DIMC];         // [n][p][c]  conv1 pre-BN
__device__ float         g_pref[(size_t)NB * HH * 129 * DIMC];  // [n][y][x+1][c]
__device__ float         g_acc[(size_t)NB * DIMC * NA * NR];    // [n][c][a][r]
__device__ float         g_h2[(size_t)NB * DIMC * NA * NR];     // conv2 pre-BN
__device__ float         g_part1[512  * DIMC * 2];
__device__ float         g_part2[2304 * DIMC * 2];
__device__ float         g_part3[2304 * DIMC * 2];
__device__ float         g_scale1[DIMC], g_shift1[DIMC];
__device__ float         g_scale2[DIMC], g_shift2[DIMC];
__device__ float         g_scale3[DIMC], g_shift3[DIMC];

// ---------------- angle tables (double, matches numpy float64) ------------
__global__ void k_tab() {
    int a = threadIdx.x;
    if (a < NA) {
        double irho = 182.0 / 191.0;
        double th = (double)a * (3.141592653589793 / 192.0);
        g_tabs[a] = sin(th) / irho;
        g_tabc[a] = cos(th) / irho;
    }
}

// ---------------- run-list builder: per (a,y) contiguous rho runs -----------
__global__ void k_runs() {
    __shared__ int sr[128];
    __shared__ int swcnt[4];
    __shared__ int swoff[4];
    int a = blockIdx.x, y = blockIdx.y;
    int x = threadIdx.x;
    double v = __dadd_rn(__dmul_rn((double)(x - WW / 2), g_tabc[a]),
                         __dmul_rn((double)(y - HH / 2), g_tabs[a]));
    int r = (int)rint(v) + NR / 2;
    r = min(max(r, 0), NR - 1);
    sr[x] = r;
    __syncthreads();
    int f = (x == 0) || (r != sr[x - 1]);
    unsigned bal = __ballot_sync(0xffffffffu, f);
    int w = x >> 5, lane = x & 31;
    int pre = __popc(bal & ((1u << lane) - 1u));
    if (lane == 31) swcnt[w] = __popc(bal);
    __syncthreads();
    if (x == 0) {
        int o = 0;
        for (int i = 0; i < 4; i++) { swoff[i] = o; o += swcnt[i]; }
        g_nrun[a * HH + y] = o;
        g_runs[((size_t)a * HH + y) * RUNCAP + o] = 128u;   // sentinel
    }
    __syncthreads();
    if (f) g_runs[((size_t)a * HH + y) * RUNCAP + swoff[w] + pre] =
               (unsigned)x | ((unsigned)r << 8);
}

// ---------------- conv1 (1x1, FFMA2) + fused BN1 partial stats --------------
__global__ __launch_bounds__(256) void k_conv1(const float* __restrict__ x,
                                               const float* __restrict__ w1,
                                               const float* __restrict__ b1) {
    __shared__ float sW[CINC * DIMC];
    __shared__ float sX[4][512];
    __shared__ float sS[DIMC], sQ[DIMC];

    int tid = threadIdx.x;
    int n  = blockIdx.x >> 5;
    int p0 = (blockIdx.x & 31) * 512;

    for (int i = tid; i < CINC * DIMC; i += 256) {
        int ci = i >> 5, d = i & 31;
        sW[i] = w1[d * CINC + ci];
    }
    if (tid < DIMC) { sS[tid] = 0.f; sQ[tid] = 0.f; }

    int pl = tid & 63;
    int d0 = (tid >> 6) * 8;

    ull acc2[8][4];
#pragma unroll
    for (int j = 0; j < 8; j++)
#pragma unroll
        for (int k = 0; k < 4; k++) acc2[j][k] = 0ull;

    const float* xb = x + (size_t)n * CINC * PIX + p0;

    for (int cc = 0; cc < CINC; cc += 4) {
        __syncthreads();
        for (int i = tid; i < 4 * 512; i += 256) {
            int cl = i >> 9, pp = i & 511;
            sX[cl][pp] = xb[(size_t)(cc + cl) * PIX + pp];
        }
        __syncthreads();
#pragma unroll
        for (int cl = 0; cl < 4; cl++) {
            float xv[8];
#pragma unroll
            for (int j = 0; j < 8; j++) xv[j] = sX[cl][pl + 64 * j];
            const ull* wp = (const ull*)&sW[(cc + cl) * DIMC + d0];
            ull w0 = wp[0], w1r = wp[1], w2 = wp[2], w3 = wp[3];
#pragma unroll
            for (int j = 0; j < 8; j++) {
                ull xp = pack2(xv[j]);
                fma2(acc2[j][0], xp, w0);
                fma2(acc2[j][1], xp, w1r);
                fma2(acc2[j][2], xp, w2);
                fma2(acc2[j][3], xp, w3);
            }
        }
    }

    float bia[8];
#pragma unroll
    for (int k = 0; k < 8; k++) bia[k] = b1[d0 + k];

    float* hb = g_h1 + ((size_t)n * PIX + p0) * DIMC;
    float sl[8], ql[8];
#pragma unroll
    for (int k = 0; k < 8; k++) { sl[k] = 0.f; ql[k] = 0.f; }

#pragma unroll
    for (int j = 0; j < 8; j++) {
        float vv[8];
#pragma unroll
        for (int k2 = 0; k2 < 4; k2++) {
            float lo, hi;
            unpack2(acc2[j][k2], lo, hi);
            vv[2 * k2]     = lo + bia[2 * k2];
            vv[2 * k2 + 1] = hi + bia[2 * k2 + 1];
        }
#pragma unroll
        for (int k = 0; k < 8; k++) { sl[k] += vv[k]; ql[k] += vv[k] * vv[k]; }
        float* op = hb + (size_t)(pl + 64 * j) * DIMC + d0;
        *(float4*)op       = make_float4(vv[0], vv[1], vv[2], vv[3]);
        *(float4*)(op + 4) = make_float4(vv[4], vv[5], vv[6], vv[7]);
    }
#pragma unroll
    for (int k = 0; k < 8; k++) {
        atomicAdd(&sS[d0 + k], sl[k]);
        atomicAdd(&sQ[d0 + k], ql[k]);
    }
    __syncthreads();
    if (tid < DIMC) {
        g_part1[(blockIdx.x * DIMC + tid) * 2 + 0] = sS[tid];
        g_part1[(blockIdx.x * DIMC + tid) * 2 + 1] = sQ[tid];
    }
}

// ---------------- BN reduce: partials -> scale/shift ------------------------
__global__ void k_red(int which, int nb, float cnt,
                      const float* __restrict__ g, const float* __restrict__ be) {
    const float* part = (which == 1) ? g_part1 : (which == 2) ? g_part2 : g_part3;
    float* sc = (which == 1) ? g_scale1 : (which == 2) ? g_scale2 : g_scale3;
    float* sh = (which == 1) ? g_shift1 : (which == 2) ? g_shift2 : g_shift3;
    __shared__ float rs[8][32], rq[8][32];
    int ch = threadIdx.x & 31, s = threadIdx.x >> 5;
    float su = 0.f, q = 0.f;
    for (int b = s; b < nb; b += 8) {
        su += part[((size_t)b * DIMC + ch) * 2 + 0];
        q  += part[((size_t)b * DIMC + ch) * 2 + 1];
    }
    rs[s][ch] = su; rq[s][ch] = q;
    __syncthreads();
    if (threadIdx.x < 32) {
        float S = 0.f, Q = 0.f;
        for (int t = 0; t < 8; t++) { S += rs[t][ch]; Q += rq[t][ch]; }
        float m   = S / cnt;
        float var = Q / cnt - m * m;
        float scv = g[ch] * rsqrtf(var + BN_EPS);
        sc[ch] = scv;
        sh[ch] = be[ch] - m * scv;
    }
}

// ---------------- row prefix sums of relu(bn(h1)) ---------------------------
__global__ __launch_bounds__(256) void k_prefix() {
    int tid = threadIdx.x;
    int w = tid >> 5, c = tid & 31;
    int row = blockIdx.x * 8 + w;                 // n*128 + y
    int n = row >> 7, y = row & 127;
    float sc = g_scale1[c], sh = g_shift1[c];
    const float* hb = g_h1 + ((size_t)n * PIX + (size_t)y * WW) * DIMC + c;
    float* pb = g_pref + (size_t)row * 129 * DIMC + c;
    float s = 0.f;
    pb[0] = 0.f;
#pragma unroll 8
    for (int x = 0; x < 128; x++) {
        float v = fmaxf(fmaf(hb[(size_t)x * DIMC], sc, sh), 0.f);
        s += v;
        pb[(size_t)(x + 1) * DIMC] = s;
    }
}

// ---------------- DHT gather: double-buffered rows, no atomics --------------
// block = (n, 4 angles), 512 threads = 16 warps, 4 warps per angle.
__global__ __launch_bounds__(512) void k_dhtg() {
    extern __shared__ float sm[];
    float*    sAcc  = sm;                                    // [4][192][36]
    float4*   sRow  = (float4*)(sm + 4 * 192 * 36);          // [2][1032]
    unsigned* sRuns = (unsigned*)(sRow + 2 * 1032);          // [2][528]
    int*      sNr   = (int*)(sRuns + 2 * 528);               // [2][4]

    int tid = threadIdx.x;
    int n = blockIdx.y, a0 = blockIdx.x * 4;

    for (int i = tid; i < 4 * 192 * 36; i += 512) sAcc[i] = 0.f;

    int w = tid >> 5, lane = tid & 31;
    int ga = w >> 2, ws = w & 3;
    int rsub = lane >> 3, c4 = lane & 7;

    const float4* prefn = (const float4*)(g_pref + (size_t)n * HH * 129 * DIMC);
    float* accA = sAcc + ga * 192 * 36;

    // prefetch registers
    float4 ra, rb, rc;
    unsigned ru0 = 0, ru1 = 0;
    int rn = 0;
    int aa0 = tid / RUNCAP, kk0 = tid - aa0 * RUNCAP;              // tid < 512 < 528
    int idx1 = tid + 512;
    int aa1 = idx1 / RUNCAP, kk1 = idx1 - aa1 * RUNCAP;

    {   // y = 0
        const float4* src = prefn;
        ra = src[tid]; rb = src[tid + 512];
        if (tid < 8) rc = src[tid + 1024];
        ru0 = g_runs[((size_t)(a0 + aa0) * HH + 0) * RUNCAP + kk0];
        if (tid < 16) ru1 = g_runs[((size_t)(a0 + aa1) * HH + 0) * RUNCAP + kk1];
        if (tid < 4)  rn  = g_nrun[(a0 + tid) * HH + 0];
    }

    for (int y = 0; y < 128; y++) {
        int bsel = y & 1;
        float4* buf = sRow + bsel * 1032;
        unsigned* rbuf = sRuns + bsel * 528;
        buf[tid] = ra; buf[tid + 512] = rb;
        if (tid < 8) buf[tid + 1024] = rc;
        rbuf[tid] = ru0;
        if (tid < 16) rbuf[512 + tid] = ru1;
        if (tid < 4)  sNr[bsel * 4 + tid] = rn;
        __syncthreads();

        if (y < 127) {   // prefetch y+1 while processing y
            const float4* src = prefn + (size_t)(y + 1) * 1032;
            ra = src[tid]; rb = src[tid + 512];
            if (tid < 8) rc = src[tid + 1024];
            ru0 = g_runs[((size_t)(a0 + aa0) * HH + (y + 1)) * RUNCAP + kk0];
            if (tid < 16) ru1 = g_runs[((size_t)(a0 + aa1) * HH + (y + 1)) * RUNCAP + kk1];
            if (tid < 4)  rn  = g_nrun[(a0 + tid) * HH + (y + 1)];
        }

        int nrun = sNr[bsel * 4 + ga];
        const unsigned* rl = rbuf + ga * RUNCAP;
        const float4* rowf = buf;
        for (int base = ws * 4 + rsub; base < nrun; base += 16) {
            unsigned rec = rl[base], nxt = rl[base + 1];
            int xs = rec & 255, xe = nxt & 255, r = (rec >> 8) & 255;
            float4 pe = rowf[xe * 8 + c4];
            float4 ps = rowf[xs * 8 + c4];
            float4* ap = (float4*)(accA + r * 36) + c4;
            float4 av = *ap;
            av.x += pe.x - ps.x; av.y += pe.y - ps.y;
            av.z += pe.z - ps.z; av.w += pe.w - ps.w;
            *ap = av;
        }
        __syncthreads();
    }

    for (int e = tid; e < 4 * DIMC * NR; e += 512) {
        int r = e % NR;
        int t = e / NR;
        int c = t & 31;
        int ga2 = t >> 5;
        g_acc[(((size_t)n * DIMC + c) * NA + (a0 + ga2)) * NR + r] =
            sAcc[(ga2 * 192 + r) * 36 + c];
    }
}

// ---------------- 3x3 conv (FFMA2) + fused BN partial stats -----------------
template <int MODE>
__global__ __launch_bounds__(256) void k_conv3x3(const float* __restrict__ w,
                                                 const float* __restrict__ b,
                                                 float* __restrict__ out_ext) {
    extern __shared__ float sm[];
    float* sIn = sm;                 // 32*18*18
    float* sW  = sm + 32 * 324;      // 32*9*32
    __shared__ float sS[DIMC], sQ[DIMC];

    int tid = threadIdx.x;
    if (tid < DIMC) { sS[tid] = 0.f; sQ[tid] = 0.f; }

    int n   = blockIdx.z;
    int ty0 = blockIdx.y * 16, tx0 = blockIdx.x * 16;

    for (int i = tid; i < 32 * 9 * 32; i += 256) {
        int d = i & 31; int t = (i >> 5) % 9; int cc = i / 288;
        sW[i] = w[((size_t)d * 32 + cc) * 9 + t];
    }

    const float* in = (MODE == 0) ? g_acc : g_h2;
    for (int i = tid; i < 32 * 324; i += 256) {
        int cc = i / 324; int rem = i % 324;
        int yy = rem / 18, xx = rem % 18;
        int gy = ty0 + yy - 1, gx = tx0 + xx - 1;
        float v = 0.f;
        if ((unsigned)gy < 192u && (unsigned)gx < 192u) {
            v = in[(((size_t)n * DIMC + cc) * 192 + gy) * 192 + gx];
            if (MODE == 1) v = fmaxf(fmaf(v, g_scale2[cc], g_shift2[cc]), 0.f);
        }
        sIn[i] = v;
    }
    __syncthreads();

    int pg = tid & 63, d0 = (tid >> 6) * 8;
    int px = pg & 15, pyb = pg >> 4;

    ull acc2[4][4];
#pragma unroll
    for (int j = 0; j < 4; j++)
#pragma unroll
        for (int k = 0; k < 4; k++) acc2[j][k] = 0ull;

    for (int cc = 0; cc < 32; cc++) {
        const float* ib = &sIn[cc * 324];
        const float* wb = &sW[cc * 288 + d0];
#pragma unroll
        for (int t = 0; t < 9; t++) {
            int ky = t / 3, kx = t % 3;
            const ull* wp = (const ull*)(wb + t * 32);
            ull w0 = wp[0], w1r = wp[1], w2 = wp[2], w3 = wp[3];
#pragma unroll
            for (int j = 0; j < 4; j++) {
                float xv = ib[(pyb + 4 * j + ky) * 18 + px + kx];
                ull xp = pack2(xv);
                fma2(acc2[j][0], xp, w0);
                fma2(acc2[j][1], xp, w1r);
                fma2(acc2[j][2], xp, w2);
                fma2(acc2[j][3], xp, w3);
            }
        }
    }

    float bia[8];
#pragma unroll
    for (int k = 0; k < 8; k++) bia[k] = b[d0 + k];

    float* outp = (MODE == 0) ? g_h2 : out_ext;
    float sl[8], ql[8];
#pragma unroll
    for (int k = 0; k < 8; k++) { sl[k] = 0.f; ql[k] = 0.f; }

#pragma unroll
    for (int j = 0; j < 4; j++) {
        int oy = ty0 + pyb + 4 * j, ox = tx0 + px;
        float vv[8];
#pragma unroll
        for (int k2 = 0; k2 < 4; k2++) {
            float lo, hi;
            unpack2(acc2[j][k2], lo, hi);
            vv[2 * k2]     = lo + bia[2 * k2];
            vv[2 * k2 + 1] = hi + bia[2 * k2 + 1];
        }
#pragma unroll
        for (int k = 0; k < 8; k++) {
            float v = vv[k];
            outp[(((size_t)n * DIMC + d0 + k) * 192 + oy) * 192 + ox] = v;
            sl[k] += v; ql[k] += v * v;
        }
    }
#pragma unroll
    for (int k = 0; k < 8; k++) {
        atomicAdd(&sS[d0 + k], sl[k]);
        atomicAdd(&sQ[d0 + k], ql[k]);
    }
    __syncthreads();
    int bid = (blockIdx.z * gridDim.y + blockIdx.y) * gridDim.x + blockIdx.x;
    float* part = (MODE == 0) ? g_part2 : g_part3;
    if (tid < DIMC) {
        part[((size_t)bid * DIMC + tid) * 2 + 0] = sS[tid];
        part[((size_t)bid * DIMC + tid) * 2 + 1] = sQ[tid];
    }
}

// ---------------- final in-place BN3 + ReLU on d_out ------------------------
__global__ void k_final(float* __restrict__ out) {
    size_t i = ((size_t)blockIdx.x * 256 + threadIdx.x) * 4;
    int c = (int)((i / APIX) & 31);
    float sc = g_scale3[c], sh = g_shift3[c];
    float4 v = *(float4*)(out + i);
    v.x = fmaxf(fmaf(v.x, sc, sh), 0.f);
    v.y = fmaxf(fmaf(v.y, sc, sh), 0.f);
    v.z = fmaxf(fmaf(v.z, sc, sh), 0.f);
    v.w = fmaxf(fmaf(v.w, sc, sh), 0.f);
    *(float4*)(out + i) = v;
}

// ---------------- launch ----------------------------------------------------
extern "C" void kernel_launch(void* const* d_in, const int* in_sizes, int n_in,
                              void* d_out, int out_size) {
    const float* x   = (const float*)d_in[0];
    const float* w1  = (const float*)d_in[1];
    const float* b1  = (const float*)d_in[2];
    const float* g1  = (const float*)d_in[3];
    const float* be1 = (const float*)d_in[4];
    const float* w2  = (const float*)d_in[5];
    const float* b2  = (const float*)d_in[6];
    const float* g2  = (const float*)d_in[7];
    const float* be2 = (const float*)d_in[8];
    const float* w3  = (const float*)d_in[9];
    const float* b3  = (const float*)d_in[10];
    const float* g3  = (const float*)d_in[11];
    const float* be3 = (const float*)d_in[12];
    float* out = (float*)d_out;

    const int dhtSmem  = 4 * 192 * 36 * 4 + 2 * 1032 * 16 + 2 * 528 * 4 + 8 * 4; // 147872
    const int convSmem = (32 * 324 + 32 * 9 * 32) * 4;                           // 78336
    cudaFuncSetAttribute(k_dhtg,       cudaFuncAttributeMaxDynamicSharedMemorySize, dhtSmem);
    cudaFuncSetAttribute(k_conv3x3<0>, cudaFuncAttributeMaxDynamicSharedMemorySize, convSmem);
    cudaFuncSetAttribute(k_conv3x3<1>, cudaFuncAttributeMaxDynamicSharedMemorySize, convSmem);

    k_tab<<<1, 192>>>();
    k_runs<<<dim3(NA, HH), 128>>>();

    k_conv1<<<512, 256>>>(x, w1, b1);
    k_red<<<1, 256>>>(1, 512, (float)(NB * PIX), g1, be1);

    k_prefix<<<256, 256>>>();
    k_dhtg<<<dim3(48, NB), 512, dhtSmem>>>();

    dim3 cgrid(12, 12, NB);
    k_conv3x3<0><<<cgrid, 256, convSmem>>>(w2, b2, nullptr);
    k_red<<<1, 256>>>(2, 2304, (float)(NB * APIX), g2, be2);

    k_conv3x3<1><<<cgrid, 256, convSmem>>>(w3, b3, out);
    k_red<<<1, 256>>>(3, 2304, (float)(NB * APIX), g3, be3);

    k_final<<<(NB * DIMC * APIX) / (256 * 4), 256>>>(out);
}